// round 13
// baseline (speedup 1.0000x reference)
#include <cuda_runtime.h>
#include <cuda_bf16.h>
#include <cstdint>

#define NUM_ITEMS 10000
#define BATCH     4096
#define DHEAD     10128   // w_head row length
#define JTILE     100     // j-columns per CTA (padded to 104 in smem)
#define NJT       100
#define NBT       32

// scratch (static __device__ arrays — no allocation)
__device__ __align__(16) __nv_bfloat16 g_h[BATCH * 128];        // 1 MB (ORIGINAL order)
__device__ __align__(16) __nv_bfloat16 g_wd[NUM_ITEMS * 128];   // 2.5 MB
__device__ int g_items[BATCH];   // sorted (ascending by item)
__device__ int g_perm[BATCH];    // sorted pos -> original batch row

__device__ __forceinline__ uint32_t smem_u32(const void* p) {
    uint32_t r;
    asm("{ .reg .u64 t; cvta.to.shared.u64 t, %1; cvt.u32.u64 %0, t; }"
        : "=r"(r) : "l"(p));
    return r;
}

__device__ __forceinline__ uint32_t bf2_as_u32(__nv_bfloat162 v) {
    return *reinterpret_cast<uint32_t*>(&v);
}

__device__ __forceinline__ void ldm_x4(uint32_t* r, uint32_t addr) {
    asm volatile("ldmatrix.sync.aligned.m8n8.x4.shared.b16 {%0,%1,%2,%3}, [%4];"
        : "=r"(r[0]), "=r"(r[1]), "=r"(r[2]), "=r"(r[3]) : "r"(addr));
}
__device__ __forceinline__ void ldm_x2(uint32_t* r, uint32_t addr) {
    asm volatile("ldmatrix.sync.aligned.m8n8.x2.shared.b16 {%0,%1}, [%2];"
        : "=r"(r[0]), "=r"(r[1]) : "r"(addr));
}
__device__ __forceinline__ void mma16816(float* c, const uint32_t* a, const uint32_t* b) {
    asm volatile(
        "mma.sync.aligned.m16n8k16.row.col.f32.bf16.bf16.f32 "
        "{%0,%1,%2,%3}, {%4,%5,%6,%7}, {%8,%9}, {%0,%1,%2,%3};"
        : "+f"(c[0]), "+f"(c[1]), "+f"(c[2]), "+f"(c[3])
        : "r"(a[0]), "r"(a[1]), "r"(a[2]), "r"(a[3]), "r"(b[0]), "r"(b[1]));
}
__device__ __forceinline__ void stcs2(float* p, float2 v) {
    asm volatile("st.global.cs.v2.f32 [%0], {%1, %2};" :: "l"(p), "f"(v.x), "f"(v.y) : "memory");
}

// sigmoid via hardware tanh: 1 MUFU instead of ex2+rcp
__device__ __forceinline__ float sigf(float x) {
    float t;
    asm("tanh.approx.f32 %0, %1;" : "=f"(t) : "f"(0.5f * x));
    return fmaf(0.5f, t, 0.5f);
}

// ============ fused prologue kernel (1024 threads) ============
// block 0          : counting-sort interactions by item -> g_items, g_perm
// blocks 1..32     : MLP on ORIGINAL-order rows -> g_h (original order)
// blocks 33..345   : w_head dense slice -> bf16 g_wd
__device__ void sort_block(const unsigned int* __restrict__ w, int tid) {
    __shared__ unsigned int hist[NUM_ITEMS];   // 40 KB static smem
    __shared__ unsigned int wsum[32];
    __shared__ int s_or;
    const int lane = tid & 31;
    if (tid == 0) s_or = 0;
    for (int i = tid; i < NUM_ITEMS; i += 1024) hist[i] = 0;
    __syncthreads();

    // dtype detect: int64 buffers have all-zero high words
    unsigned int acc = 0;
    #pragma unroll
    for (int k = 0; k < 4; k++) acc |= w[2 * (tid + k * 1024) + 1];
    if (acc) atomicOr(&s_or, 1);
    __syncthreads();
    const bool is64 = (s_or == 0);

    int myit[4];
    #pragma unroll
    for (int k = 0; k < 4; k++) {
        int r = tid + k * 1024;
        myit[k] = is64 ? (int)w[4 * r + 2] : (int)w[2 * r + 1];
        atomicAdd(&hist[myit[k]], 1u);
    }
    __syncthreads();

    // exclusive prefix sum over 10000 bins: 10 bins/thread + warp-shuffle scan
    const int base = tid * 10;
    unsigned int local[10];
    unsigned int sum = 0;
    #pragma unroll
    for (int k = 0; k < 10; k++) {
        int i = base + k;
        unsigned int v = (i < NUM_ITEMS) ? hist[i] : 0;
        local[k] = sum; sum += v;
    }
    unsigned int inc = sum;
    #pragma unroll
    for (int off = 1; off < 32; off <<= 1) {
        unsigned int v = __shfl_up_sync(0xffffffffu, inc, off);
        if (lane >= off) inc += v;
    }
    if (lane == 31) wsum[tid >> 5] = inc;
    __syncthreads();
    if (tid < 32) {
        unsigned int v = wsum[tid];
        unsigned int i2 = v;
        #pragma unroll
        for (int off = 1; off < 32; off <<= 1) {
            unsigned int u = __shfl_up_sync(0xffffffffu, i2, off);
            if (tid >= off) i2 += u;
        }
        wsum[tid] = i2 - v;   // exclusive warp base
    }
    __syncthreads();
    unsigned int tbase = wsum[tid >> 5] + (inc - sum);
    #pragma unroll
    for (int k = 0; k < 10; k++) {
        int i = base + k;
        if (i < NUM_ITEMS) hist[i] = tbase + local[k];
    }
    __syncthreads();

    // scatter into sorted arrays
    #pragma unroll
    for (int k = 0; k < 4; k++) {
        int r = tid + k * 1024;
        unsigned int pos = atomicAdd(&hist[myit[k]], 1u);
        g_items[pos] = myit[k];
        g_perm[pos]  = r;
    }
}

__global__ void __launch_bounds__(1024, 1) mid_kernel(
    const unsigned int* __restrict__ w,
    const float* __restrict__ uemb, const float* __restrict__ iemb,
    const float* __restrict__ w1, const float* __restrict__ b1,
    const float* __restrict__ w2, const float* __restrict__ b2,
    const float* __restrict__ w_head)
{
    const int tid = threadIdx.x;
    const int blk = blockIdx.x;

    if (blk == 0) { sort_block(w, tid); return; }

    if (blk >= 33) {
        // ---- conv: w_head dense slice -> bf16, 4096 elements/block ----
        int idx = (blk - 33) * 4096 + tid * 4;      // 313 blocks cover 1,280,000
        if (idx < NUM_ITEMS * 128) {
            int j = idx >> 7, k = idx & 127;
            float4 v = *reinterpret_cast<const float4*>(
                w_head + (size_t)j * DHEAD + NUM_ITEMS + k);
            uint2 o;
            o.x = bf2_as_u32(__floats2bfloat162_rn(v.x, v.y));
            o.y = bf2_as_u32(__floats2bfloat162_rn(v.z, v.w));
            *reinterpret_cast<uint2*>(g_wd + idx) = o;
        }
        return;
    }

    // ---- MLP: 32 warps x 4 ORIGINAL-order rows; weights transposed in smem ----
    extern __shared__ char dynsm[];
    float* smf = reinterpret_cast<float*>(dynsm);
    float* w1t = smf;            // [64][128]
    float* w2t = smf + 64 * 128; // [128][128]
    __shared__ int s_or;
    if (tid == 0) s_or = 0;
    __syncthreads();
    if (w[2 * tid + 1]) atomicOr(&s_or, 1);   // dtype detect: 1024 samples

    for (int idx = tid; idx < 128 * 64; idx += 1024)
        w1t[(idx & 63) * 128 + (idx >> 6)] = w1[idx];
    for (int idx = tid; idx < 128 * 128; idx += 1024)
        w2t[(idx & 127) * 128 + (idx >> 7)] = w2[idx];
    __syncthreads();
    const bool is64 = (s_or == 0);

    const int lane = tid & 31;
    const int r0 = ((blk - 1) * 32 + (tid >> 5)) * 4;

    float e0[4], e1[4];
    #pragma unroll
    for (int i = 0; i < 4; i++) {
        int r = r0 + i;
        int u, it;
        if (is64) { u = (int)w[4 * r]; it = (int)w[4 * r + 2]; }
        else      { u = (int)w[2 * r]; it = (int)w[2 * r + 1]; }
        e0[i] = uemb[u * 32 + lane];
        e1[i] = iemb[it * 32 + lane];
    }

    float4 bias1 = reinterpret_cast<const float4*>(b1)[lane];
    float4 acc[4];
    #pragma unroll
    for (int i = 0; i < 4; i++) acc[i] = bias1;

    #pragma unroll 4
    for (int kq = 0; kq < 16; kq++) {
        float4 wr[4];
        #pragma unroll
        for (int c = 0; c < 4; c++)
            wr[c] = reinterpret_cast<const float4*>(w1t + (4 * kq + c) * 128)[lane];
        #pragma unroll
        for (int i = 0; i < 4; i++) {
            float src = (kq < 8) ? e0[i] : e1[i];
            #pragma unroll
            for (int c = 0; c < 4; c++) {
                float v = __shfl_sync(0xffffffffu, src, (4 * kq + c) & 31);
                acc[i].x = fmaf(v, wr[c].x, acc[i].x);
                acc[i].y = fmaf(v, wr[c].y, acc[i].y);
                acc[i].z = fmaf(v, wr[c].z, acc[i].z);
                acc[i].w = fmaf(v, wr[c].w, acc[i].w);
            }
        }
    }

    float4 h1[4];
    #pragma unroll
    for (int i = 0; i < 4; i++) {
        h1[i].x = fmaxf(acc[i].x, 0.f);
        h1[i].y = fmaxf(acc[i].y, 0.f);
        h1[i].z = fmaxf(acc[i].z, 0.f);
        h1[i].w = fmaxf(acc[i].w, 0.f);
    }

    float4 bias2 = reinterpret_cast<const float4*>(b2)[lane];
    float4 acc2[4];
    #pragma unroll
    for (int i = 0; i < 4; i++) acc2[i] = bias2;

    #pragma unroll 4
    for (int kq = 0; kq < 32; kq++) {
        float4 wr[4];
        #pragma unroll
        for (int c = 0; c < 4; c++)
            wr[c] = reinterpret_cast<const float4*>(w2t + (4 * kq + c) * 128)[lane];
        #pragma unroll
        for (int i = 0; i < 4; i++) {
            float vx = __shfl_sync(0xffffffffu, h1[i].x, kq);
            float vy = __shfl_sync(0xffffffffu, h1[i].y, kq);
            float vz = __shfl_sync(0xffffffffu, h1[i].z, kq);
            float vw = __shfl_sync(0xffffffffu, h1[i].w, kq);
            acc2[i].x = fmaf(vx, wr[0].x, acc2[i].x);
            acc2[i].y = fmaf(vx, wr[0].y, acc2[i].y);
            acc2[i].z = fmaf(vx, wr[0].z, acc2[i].z);
            acc2[i].w = fmaf(vx, wr[0].w, acc2[i].w);
            acc2[i].x = fmaf(vy, wr[1].x, acc2[i].x);
            acc2[i].y = fmaf(vy, wr[1].y, acc2[i].y);
            acc2[i].z = fmaf(vy, wr[1].z, acc2[i].z);
            acc2[i].w = fmaf(vy, wr[1].w, acc2[i].w);
            acc2[i].x = fmaf(vz, wr[2].x, acc2[i].x);
            acc2[i].y = fmaf(vz, wr[2].y, acc2[i].y);
            acc2[i].z = fmaf(vz, wr[2].z, acc2[i].z);
            acc2[i].w = fmaf(vz, wr[2].w, acc2[i].w);
            acc2[i].x = fmaf(vw, wr[3].x, acc2[i].x);
            acc2[i].y = fmaf(vw, wr[3].y, acc2[i].y);
            acc2[i].z = fmaf(vw, wr[3].z, acc2[i].z);
            acc2[i].w = fmaf(vw, wr[3].w, acc2[i].w);
        }
    }

    #pragma unroll
    for (int i = 0; i < 4; i++) {
        __nv_bfloat162 lo = __floats2bfloat162_rn(fmaxf(acc2[i].x, 0.f), fmaxf(acc2[i].y, 0.f));
        __nv_bfloat162 hi = __floats2bfloat162_rn(fmaxf(acc2[i].z, 0.f), fmaxf(acc2[i].w, 0.f));
        __nv_bfloat16* dst = g_h + (size_t)(r0 + i) * 128 + 4 * lane;
        *reinterpret_cast<__nv_bfloat162*>(dst)     = lo;
        *reinterpret_cast<__nv_bfloat162*>(dst + 2) = hi;
    }
}

// ================= kernel B: HMMA GEMM + cross-gather + sigmoid ==================
// CTA tile: M=128 x N=100 (padded 104) x K=128. 3 CTAs/SM -> 24 warps.
#define NPAD          104
#define NITER         13                          // 12 full n8 + 1 half tile
#define OFF_B_BYTES   32768                       // after A (128*128*2)
#define OFF_BIAS      (OFF_B_BYTES + NPAD * 256)  // 59392
#define SMEM_HEAD     (OFF_BIAS + NPAD * 4)       // 59808 B -> 3 CTAs/SM

__global__ void __launch_bounds__(256, 3) head_kernel(
    const float* __restrict__ w_head,
    const float* __restrict__ b_head,
    float* __restrict__ out)
{
    extern __shared__ char dynsm[];
    char* sm = dynsm;
    float* sbias = reinterpret_cast<float*>(sm + OFF_BIAS);

    const int tid  = threadIdx.x;
    const int wid  = tid >> 5;
    const int lane = tid & 31;
    const int bt   = blockIdx.x;   // 0..31  (fastest -> L2 reuse of jt slice)
    const int jt   = blockIdx.y;   // 0..99

    // ---- stage A tile: h rows via perm (g_h is original order, L2-resident) ----
    {
        uint4* sA = reinterpret_cast<uint4*>(sm);
        #pragma unroll
        for (int i = tid; i < 2048; i += 256) {
            int row = i >> 4, ch = i & 15;
            int orow = g_perm[bt * 128 + row];
            uint4 v = reinterpret_cast<const uint4*>(g_h + (size_t)orow * 128)[ch];
            sA[row * 16 + (ch ^ (row & 7))] = v;
        }
    }
    // ---- stage B tile: wd[jt*100 .. +100, 0..128) bf16, rows 100..103 zero ----
    {
        const uint4* gB = reinterpret_cast<const uint4*>(g_wd + (size_t)jt * JTILE * 128);
        uint4* sB = reinterpret_cast<uint4*>(sm + OFF_B_BYTES);
        for (int i = tid; i < NPAD * 16; i += 256) {
            int row = i >> 4, ch = i & 15;
            uint4 v = make_uint4(0u, 0u, 0u, 0u);
            if (row < JTILE) v = gB[i];
            sB[row * 16 + (ch ^ (row & 7))] = v;
        }
    }
    for (int i = tid; i < NPAD; i += 256)
        sbias[i] = (i < JTILE) ? b_head[jt * JTILE + i] : 0.0f;
    __syncthreads();

    // ---- A fragments for all 8 k-steps (register-resident) ----
    const uint32_t smA = smem_u32(sm);
    const uint32_t smB = smA + OFF_B_BYTES;
    uint32_t a[8][4];
    {
        int arow = wid * 16 + (lane & 15);
        int csel = lane >> 4;
        uint32_t rowaddr = smA + arow * 256;
        #pragma unroll
        for (int k = 0; k < 8; k++) {
            int ch = 2 * k + csel;
            ldm_x4(a[k], rowaddr + ((ch ^ (arow & 7)) << 4));
        }
    }

    // per-thread output coordinates (sorted space; outputs scatter via g_perm)
    const int r1   = bt * 128 + wid * 16 + (lane >> 2);
    const int r2   = r1 + 8;
    const int it1  = g_items[r1];          // sorted: lanes' items are clustered
    const int it2  = g_items[r2];
    const int jloc = (lane & 3) * 2;
    const int jbase = jt * JTILE;
    float* out1 = out + (size_t)g_perm[r1] * NUM_ITEMS + jbase;
    float* out2 = out + (size_t)g_perm[r2] * NUM_ITEMS + jbase;

    const int bro = (lane & 7);
    const int bco = (lane >> 3) & 1;

    // gather prefetch, distance 3 (j clamped: pad cols never stored)
    auto gload = [&](int n, float* g) {
        int j0 = jbase + n * 8 + jloc;
        int j1 = j0 + 1;
        if (j0 > NUM_ITEMS - 1) j0 = NUM_ITEMS - 1;
        if (j1 > NUM_ITEMS - 1) j1 = NUM_ITEMS - 1;
        const float* w0 = w_head + (size_t)j0 * DHEAD;
        const float* w1p = w_head + (size_t)j1 * DHEAD;
        g[0] = __ldg(w0 + it1);
        g[1] = __ldg(w1p + it1);
        g[2] = __ldg(w0 + it2);
        g[3] = __ldg(w1p + it2);
    };
    float ga[4], gb[4], gc[4];
    gload(0, ga);
    gload(1, gb);
    gload(2, gc);

    #pragma unroll 1
    for (int n = 0; n < NITER; n++) {
        float c[4] = {0.f, 0.f, 0.f, 0.f};
        int brow = n * 8 + bro;
        uint32_t baddr_row = smB + brow * 256;
        #pragma unroll
        for (int k = 0; k < 8; k++) {
            uint32_t b[2];
            int ch = 2 * k + bco;
            ldm_x2(b, baddr_row + ((ch ^ (brow & 7)) << 4));
            mma16816(c, a[k], b);
        }
        float h00 = ga[0], h01 = ga[1], h10 = ga[2], h11 = ga[3];
        #pragma unroll
        for (int q2 = 0; q2 < 4; q2++) { ga[q2] = gb[q2]; gb[q2] = gc[q2]; }
        if (n + 3 < NITER) gload(n + 3, gc);

        int jc = n * 8 + jloc;
        float b0 = sbias[jc], b1 = sbias[jc + 1];
        float2 o1, o2;
        o1.x = sigf(c[0] + b0 + h00);
        o1.y = sigf(c[1] + b1 + h01);
        o2.x = sigf(c[2] + b0 + h10);
        o2.y = sigf(c[3] + b1 + h11);
        if (jc < JTILE) {           // last (half) tile: cols 100..103 are pad
            stcs2(out1 + jc, o1);
            stcs2(out2 + jc, o2);
        }
    }
}

// ================================ launch ================================
extern "C" void kernel_launch(void* const* d_in, const int* in_sizes, int n_in,
                              void* d_out, int out_size) {
    (void)in_sizes; (void)n_in; (void)out_size;
    const unsigned int* inter_w = (const unsigned int*)d_in[0];
    const float* uemb   = (const float*)d_in[1];
    const float* iemb   = (const float*)d_in[2];
    const float* w1     = (const float*)d_in[3];
    const float* b1     = (const float*)d_in[4];
    const float* w2     = (const float*)d_in[5];
    const float* b2     = (const float*)d_in[6];
    const float* w_head = (const float*)d_in[7];
    const float* b_head = (const float*)d_in[8];
    float* out = (float*)d_out;

    cudaFuncSetAttribute(mid_kernel,  cudaFuncAttributeMaxDynamicSharedMemorySize, 98304);
    cudaFuncSetAttribute(head_kernel, cudaFuncAttributeMaxDynamicSharedMemorySize, SMEM_HEAD);

    mid_kernel<<<346, 1024, 98304>>>(inter_w, uemb, iemb, w1, b1, w2, b2, w_head);
    head_kernel<<<dim3(NBT, NJT), 256, SMEM_HEAD>>>(w_head, b_head, out);
}

// round 14
// speedup vs baseline: 1.0649x; 1.0649x over previous
#include <cuda_runtime.h>
#include <cuda_bf16.h>
#include <cstdint>

#define NUM_ITEMS 10000
#define BATCH     4096
#define DHEAD     10128   // w_head row length
#define JTILE     100     // j-columns per CTA (padded to 104 in smem)
#define NJT       100
#define NBT       32

// scratch (static __device__ arrays — no allocation)
__device__ __align__(16) __nv_bfloat16 g_h[BATCH * 128];        // 1 MB (ORIGINAL order)
__device__ __align__(16) __nv_bfloat16 g_wd[NUM_ITEMS * 128];   // 2.5 MB
__device__ int g_items[BATCH];   // sorted (ascending by item)
__device__ int g_perm[BATCH];    // sorted pos -> original batch row

__device__ __forceinline__ uint32_t smem_u32(const void* p) {
    uint32_t r;
    asm("{ .reg .u64 t; cvta.to.shared.u64 t, %1; cvt.u32.u64 %0, t; }"
        : "=r"(r) : "l"(p));
    return r;
}

__device__ __forceinline__ uint32_t bf2_as_u32(__nv_bfloat162 v) {
    return *reinterpret_cast<uint32_t*>(&v);
}

__device__ __forceinline__ void ldm_x4(uint32_t* r, uint32_t addr) {
    asm volatile("ldmatrix.sync.aligned.m8n8.x4.shared.b16 {%0,%1,%2,%3}, [%4];"
        : "=r"(r[0]), "=r"(r[1]), "=r"(r[2]), "=r"(r[3]) : "r"(addr));
}
__device__ __forceinline__ void ldm_x2(uint32_t* r, uint32_t addr) {
    asm volatile("ldmatrix.sync.aligned.m8n8.x2.shared.b16 {%0,%1}, [%2];"
        : "=r"(r[0]), "=r"(r[1]) : "r"(addr));
}
__device__ __forceinline__ void mma16816(float* c, const uint32_t* a, const uint32_t* b) {
    asm volatile(
        "mma.sync.aligned.m16n8k16.row.col.f32.bf16.bf16.f32 "
        "{%0,%1,%2,%3}, {%4,%5,%6,%7}, {%8,%9}, {%0,%1,%2,%3};"
        : "+f"(c[0]), "+f"(c[1]), "+f"(c[2]), "+f"(c[3])
        : "r"(a[0]), "r"(a[1]), "r"(a[2]), "r"(a[3]), "r"(b[0]), "r"(b[1]));
}
__device__ __forceinline__ void stcs2(float* p, float2 v) {
    asm volatile("st.global.cs.v2.f32 [%0], {%1, %2};" :: "l"(p), "f"(v.x), "f"(v.y) : "memory");
}

// sigmoid via hardware tanh: 1 MUFU instead of ex2+rcp
__device__ __forceinline__ float sigf(float x) {
    float t;
    asm("tanh.approx.f32 %0, %1;" : "=f"(t) : "f"(0.5f * x));
    return fmaf(0.5f, t, 0.5f);
}

// ============ fused prologue kernel (512 threads) ============
// block 0          : counting-sort interactions by item -> g_items, g_perm
// blocks 1..64     : MLP on ORIGINAL-order rows -> g_h (original order)
// blocks 65..689   : w_head dense slice -> bf16 g_wd
__device__ void sort_block(const unsigned int* __restrict__ w, int tid) {
    __shared__ unsigned int hist[NUM_ITEMS];   // 40 KB static smem
    __shared__ unsigned int wsum[16];
    __shared__ int s_or;
    const int lane = tid & 31;
    if (tid == 0) s_or = 0;
    for (int i = tid; i < NUM_ITEMS; i += 512) hist[i] = 0;
    __syncthreads();

    // dtype detect: int64 buffers have all-zero high words
    unsigned int acc = 0;
    #pragma unroll
    for (int k = 0; k < 8; k++) acc |= w[2 * (tid + k * 512) + 1];
    if (acc) atomicOr(&s_or, 1);
    __syncthreads();
    const bool is64 = (s_or == 0);

    int myit[8];
    #pragma unroll
    for (int k = 0; k < 8; k++) {
        int r = tid + k * 512;
        myit[k] = is64 ? (int)w[4 * r + 2] : (int)w[2 * r + 1];
        atomicAdd(&hist[myit[k]], 1u);
    }
    __syncthreads();

    // exclusive prefix sum over 10000 bins: 20 bins/thread + warp-shuffle scan
    const int base = tid * 20;
    unsigned int local[20];
    unsigned int sum = 0;
    #pragma unroll
    for (int k = 0; k < 20; k++) {
        int i = base + k;
        unsigned int v = (i < NUM_ITEMS) ? hist[i] : 0;
        local[k] = sum; sum += v;
    }
    unsigned int inc = sum;
    #pragma unroll
    for (int off = 1; off < 32; off <<= 1) {
        unsigned int v = __shfl_up_sync(0xffffffffu, inc, off);
        if (lane >= off) inc += v;
    }
    if (lane == 31) wsum[tid >> 5] = inc;
    __syncthreads();
    if (tid < 32) {
        unsigned int v = (tid < 16) ? wsum[tid] : 0;
        unsigned int i2 = v;
        #pragma unroll
        for (int off = 1; off < 32; off <<= 1) {
            unsigned int u = __shfl_up_sync(0xffffffffu, i2, off);
            if (tid >= off) i2 += u;
        }
        if (tid < 16) wsum[tid] = i2 - v;   // exclusive warp base
    }
    __syncthreads();
    unsigned int tbase = wsum[tid >> 5] + (inc - sum);
    #pragma unroll
    for (int k = 0; k < 20; k++) {
        int i = base + k;
        if (i < NUM_ITEMS) hist[i] = tbase + local[k];
    }
    __syncthreads();

    // scatter into sorted arrays
    #pragma unroll
    for (int k = 0; k < 8; k++) {
        int r = tid + k * 512;
        unsigned int pos = atomicAdd(&hist[myit[k]], 1u);
        g_items[pos] = myit[k];
        g_perm[pos]  = r;
    }
}

__global__ void __launch_bounds__(512, 1) mid_kernel(
    const unsigned int* __restrict__ w,
    const float* __restrict__ uemb, const float* __restrict__ iemb,
    const float* __restrict__ w1, const float* __restrict__ b1,
    const float* __restrict__ w2, const float* __restrict__ b2,
    const float* __restrict__ w_head)
{
    const int tid = threadIdx.x;
    const int blk = blockIdx.x;

    if (blk == 0) { sort_block(w, tid); return; }

    if (blk >= 65) {
        // ---- conv: w_head dense slice -> bf16, 2048 elements/block ----
        int idx = (blk - 65) * 2048 + tid * 4;      // 625 blocks cover 1,280,000
        int j = idx >> 7, k = idx & 127;
        float4 v = *reinterpret_cast<const float4*>(
            w_head + (size_t)j * DHEAD + NUM_ITEMS + k);
        uint2 o;
        o.x = bf2_as_u32(__floats2bfloat162_rn(v.x, v.y));
        o.y = bf2_as_u32(__floats2bfloat162_rn(v.z, v.w));
        *reinterpret_cast<uint2*>(g_wd + idx) = o;
        return;
    }

    // ---- MLP: 16 warps x 4 ORIGINAL-order rows; weights transposed in smem ----
    extern __shared__ char dynsm[];
    float* smf = reinterpret_cast<float*>(dynsm);
    float* w1t = smf;            // [64][128]
    float* w2t = smf + 64 * 128; // [128][128]
    __shared__ int s_or;
    if (tid == 0) s_or = 0;
    __syncthreads();
    if (w[2 * tid + 1]) atomicOr(&s_or, 1);   // dtype detect: 512 samples

    for (int idx = tid; idx < 128 * 64; idx += 512)
        w1t[(idx & 63) * 128 + (idx >> 6)] = w1[idx];
    for (int idx = tid; idx < 128 * 128; idx += 512)
        w2t[(idx & 127) * 128 + (idx >> 7)] = w2[idx];
    __syncthreads();
    const bool is64 = (s_or == 0);

    const int lane = tid & 31;
    const int r0 = ((blk - 1) * 16 + (tid >> 5)) * 4;

    float e0[4], e1[4];
    #pragma unroll
    for (int i = 0; i < 4; i++) {
        int r = r0 + i;
        int u, it;
        if (is64) { u = (int)w[4 * r]; it = (int)w[4 * r + 2]; }
        else      { u = (int)w[2 * r]; it = (int)w[2 * r + 1]; }
        e0[i] = uemb[u * 32 + lane];
        e1[i] = iemb[it * 32 + lane];
    }

    float4 bias1 = reinterpret_cast<const float4*>(b1)[lane];
    float4 acc[4];
    #pragma unroll
    for (int i = 0; i < 4; i++) acc[i] = bias1;

    #pragma unroll 4
    for (int kq = 0; kq < 16; kq++) {
        float4 wr[4];
        #pragma unroll
        for (int c = 0; c < 4; c++)
            wr[c] = reinterpret_cast<const float4*>(w1t + (4 * kq + c) * 128)[lane];
        #pragma unroll
        for (int i = 0; i < 4; i++) {
            float src = (kq < 8) ? e0[i] : e1[i];
            #pragma unroll
            for (int c = 0; c < 4; c++) {
                float v = __shfl_sync(0xffffffffu, src, (4 * kq + c) & 31);
                acc[i].x = fmaf(v, wr[c].x, acc[i].x);
                acc[i].y = fmaf(v, wr[c].y, acc[i].y);
                acc[i].z = fmaf(v, wr[c].z, acc[i].z);
                acc[i].w = fmaf(v, wr[c].w, acc[i].w);
            }
        }
    }

    float4 h1[4];
    #pragma unroll
    for (int i = 0; i < 4; i++) {
        h1[i].x = fmaxf(acc[i].x, 0.f);
        h1[i].y = fmaxf(acc[i].y, 0.f);
        h1[i].z = fmaxf(acc[i].z, 0.f);
        h1[i].w = fmaxf(acc[i].w, 0.f);
    }

    float4 bias2 = reinterpret_cast<const float4*>(b2)[lane];
    float4 acc2[4];
    #pragma unroll
    for (int i = 0; i < 4; i++) acc2[i] = bias2;

    #pragma unroll 4
    for (int kq = 0; kq < 32; kq++) {
        float4 wr[4];
        #pragma unroll
        for (int c = 0; c < 4; c++)
            wr[c] = reinterpret_cast<const float4*>(w2t + (4 * kq + c) * 128)[lane];
        #pragma unroll
        for (int i = 0; i < 4; i++) {
            float vx = __shfl_sync(0xffffffffu, h1[i].x, kq);
            float vy = __shfl_sync(0xffffffffu, h1[i].y, kq);
            float vz = __shfl_sync(0xffffffffu, h1[i].z, kq);
            float vw = __shfl_sync(0xffffffffu, h1[i].w, kq);
            acc2[i].x = fmaf(vx, wr[0].x, acc2[i].x);
            acc2[i].y = fmaf(vx, wr[0].y, acc2[i].y);
            acc2[i].z = fmaf(vx, wr[0].z, acc2[i].z);
            acc2[i].w = fmaf(vx, wr[0].w, acc2[i].w);
            acc2[i].x = fmaf(vy, wr[1].x, acc2[i].x);
            acc2[i].y = fmaf(vy, wr[1].y, acc2[i].y);
            acc2[i].z = fmaf(vy, wr[1].z, acc2[i].z);
            acc2[i].w = fmaf(vy, wr[1].w, acc2[i].w);
            acc2[i].x = fmaf(vz, wr[2].x, acc2[i].x);
            acc2[i].y = fmaf(vz, wr[2].y, acc2[i].y);
            acc2[i].z = fmaf(vz, wr[2].z, acc2[i].z);
            acc2[i].w = fmaf(vz, wr[2].w, acc2[i].w);
            acc2[i].x = fmaf(vw, wr[3].x, acc2[i].x);
            acc2[i].y = fmaf(vw, wr[3].y, acc2[i].y);
            acc2[i].z = fmaf(vw, wr[3].z, acc2[i].z);
            acc2[i].w = fmaf(vw, wr[3].w, acc2[i].w);
        }
    }

    #pragma unroll
    for (int i = 0; i < 4; i++) {
        __nv_bfloat162 lo = __floats2bfloat162_rn(fmaxf(acc2[i].x, 0.f), fmaxf(acc2[i].y, 0.f));
        __nv_bfloat162 hi = __floats2bfloat162_rn(fmaxf(acc2[i].z, 0.f), fmaxf(acc2[i].w, 0.f));
        __nv_bfloat16* dst = g_h + (size_t)(r0 + i) * 128 + 4 * lane;
        *reinterpret_cast<__nv_bfloat162*>(dst)     = lo;
        *reinterpret_cast<__nv_bfloat162*>(dst + 2) = hi;
    }
}

// ================= kernel B: HMMA GEMM + cross-gather + sigmoid ==================
// CTA tile: M=128 x N=100 (padded 104) x K=128. 3 CTAs/SM -> 24 warps.
#define NPAD          104
#define NITER         13                          // 12 full n8 + 1 half tile
#define OFF_B_BYTES   32768                       // after A (128*128*2)
#define OFF_BIAS      (OFF_B_BYTES + NPAD * 256)  // 59392
#define SMEM_HEAD     (OFF_BIAS + NPAD * 4)       // 59808 B -> 3 CTAs/SM

__global__ void __launch_bounds__(256, 3) head_kernel(
    const float* __restrict__ w_head,
    const float* __restrict__ b_head,
    float* __restrict__ out)
{
    extern __shared__ char dynsm[];
    char* sm = dynsm;
    float* sbias = reinterpret_cast<float*>(sm + OFF_BIAS);

    const int tid  = threadIdx.x;
    const int wid  = tid >> 5;
    const int lane = tid & 31;
    const int bt   = blockIdx.x;   // 0..31  (fastest -> L2 reuse of jt slice)
    const int jt   = blockIdx.y;   // 0..99

    // ---- stage A tile: h rows via perm (g_h is original order, L2-resident) ----
    {
        uint4* sA = reinterpret_cast<uint4*>(sm);
        #pragma unroll
        for (int i = tid; i < 2048; i += 256) {
            int row = i >> 4, ch = i & 15;
            int orow = g_perm[bt * 128 + row];
            uint4 v = reinterpret_cast<const uint4*>(g_h + (size_t)orow * 128)[ch];
            sA[row * 16 + (ch ^ (row & 7))] = v;
        }
    }
    // ---- stage B tile: wd[jt*100 .. +100, 0..128) bf16, rows 100..103 zero ----
    {
        const uint4* gB = reinterpret_cast<const uint4*>(g_wd + (size_t)jt * JTILE * 128);
        uint4* sB = reinterpret_cast<uint4*>(sm + OFF_B_BYTES);
        for (int i = tid; i < NPAD * 16; i += 256) {
            int row = i >> 4, ch = i & 15;
            uint4 v = make_uint4(0u, 0u, 0u, 0u);
            if (row < JTILE) v = gB[i];
            sB[row * 16 + (ch ^ (row & 7))] = v;
        }
    }
    for (int i = tid; i < NPAD; i += 256)
        sbias[i] = (i < JTILE) ? b_head[jt * JTILE + i] : 0.0f;
    __syncthreads();

    // ---- A fragments for all 8 k-steps (register-resident) ----
    const uint32_t smA = smem_u32(sm);
    const uint32_t smB = smA + OFF_B_BYTES;
    uint32_t a[8][4];
    {
        int arow = wid * 16 + (lane & 15);
        int csel = lane >> 4;
        uint32_t rowaddr = smA + arow * 256;
        #pragma unroll
        for (int k = 0; k < 8; k++) {
            int ch = 2 * k + csel;
            ldm_x4(a[k], rowaddr + ((ch ^ (arow & 7)) << 4));
        }
    }

    // per-thread output coordinates (sorted space; outputs scatter via g_perm)
    const int r1   = bt * 128 + wid * 16 + (lane >> 2);
    const int r2   = r1 + 8;
    const int it1  = g_items[r1];          // sorted: lanes' items are clustered
    const int it2  = g_items[r2];
    const int jloc = (lane & 3) * 2;
    const int jbase = jt * JTILE;
    float* out1 = out + (size_t)g_perm[r1] * NUM_ITEMS + jbase;
    float* out2 = out + (size_t)g_perm[r2] * NUM_ITEMS + jbase;

    const int bro = (lane & 7);
    const int bco = (lane >> 3) & 1;

    // gather prefetch, distance 3 (j clamped: pad cols never stored)
    auto gload = [&](int n, float* g) {
        int j0 = jbase + n * 8 + jloc;
        int j1 = j0 + 1;
        if (j0 > NUM_ITEMS - 1) j0 = NUM_ITEMS - 1;
        if (j1 > NUM_ITEMS - 1) j1 = NUM_ITEMS - 1;
        const float* w0 = w_head + (size_t)j0 * DHEAD;
        const float* w1p = w_head + (size_t)j1 * DHEAD;
        g[0] = __ldg(w0 + it1);
        g[1] = __ldg(w1p + it1);
        g[2] = __ldg(w0 + it2);
        g[3] = __ldg(w1p + it2);
    };
    float ga[4], gb[4], gc[4];
    gload(0, ga);
    gload(1, gb);
    gload(2, gc);

    #pragma unroll 1
    for (int n = 0; n < NITER; n++) {
        float c[4] = {0.f, 0.f, 0.f, 0.f};
        int brow = n * 8 + bro;
        uint32_t baddr_row = smB + brow * 256;
        #pragma unroll
        for (int k = 0; k < 8; k++) {
            uint32_t b[2];
            int ch = 2 * k + bco;
            ldm_x2(b, baddr_row + ((ch ^ (brow & 7)) << 4));
            mma16816(c, a[k], b);
        }
        float h00 = ga[0], h01 = ga[1], h10 = ga[2], h11 = ga[3];
        #pragma unroll
        for (int q2 = 0; q2 < 4; q2++) { ga[q2] = gb[q2]; gb[q2] = gc[q2]; }
        if (n + 3 < NITER) gload(n + 3, gc);

        int jc = n * 8 + jloc;
        float b0 = sbias[jc], b1 = sbias[jc + 1];
        float2 o1, o2;
        o1.x = sigf(c[0] + b0 + h00);
        o1.y = sigf(c[1] + b1 + h01);
        o2.x = sigf(c[2] + b0 + h10);
        o2.y = sigf(c[3] + b1 + h11);
        if (jc < JTILE) {           // last (half) tile: cols 100..103 are pad
            stcs2(out1 + jc, o1);
            stcs2(out2 + jc, o2);
        }
    }
}

// ================================ launch ================================
extern "C" void kernel_launch(void* const* d_in, const int* in_sizes, int n_in,
                              void* d_out, int out_size) {
    (void)in_sizes; (void)n_in; (void)out_size;
    const unsigned int* inter_w = (const unsigned int*)d_in[0];
    const float* uemb   = (const float*)d_in[1];
    const float* iemb   = (const float*)d_in[2];
    const float* w1     = (const float*)d_in[3];
    const float* b1     = (const float*)d_in[4];
    const float* w2     = (const float*)d_in[5];
    const float* b2     = (const float*)d_in[6];
    const float* w_head = (const float*)d_in[7];
    const float* b_head = (const float*)d_in[8];
    float* out = (float*)d_out;

    cudaFuncSetAttribute(mid_kernel,  cudaFuncAttributeMaxDynamicSharedMemorySize, 98304);
    cudaFuncSetAttribute(head_kernel, cudaFuncAttributeMaxDynamicSharedMemorySize, SMEM_HEAD);

    mid_kernel<<<690, 512, 98304>>>(inter_w, uemb, iemb, w1, b1, w2, b2, w_head);
    head_kernel<<<dim3(NBT, NJT), 256, SMEM_HEAD>>>(w_head, b_head, out);
}